// round 13
// baseline (speedup 1.0000x reference)
#include <cuda_runtime.h>
#include <math_constants.h>

// Static problem shape: N=65536 points, 16 segments of 4096, D=3, K=20.
#define KNN 20
#define NPTS 65536
#define SEG 4096
#define QPB 128
#define TILE 2048
#define BUFCAP 20
#define NPH 15

typedef unsigned long long u64;

// ---- packed f32x2 helpers (sm_103a) ----
__device__ __forceinline__ u64 pk2(float lo, float hi) {
    u64 r;
    asm("mov.b64 %0, {%1, %2};" : "=l"(r) : "f"(lo), "f"(hi));
    return r;
}
__device__ __forceinline__ void upk2(float& lo, float& hi, u64 v) {
    asm("mov.b64 {%0, %1}, %2;" : "=f"(lo), "=f"(hi) : "l"(v));
}
__device__ __forceinline__ u64 add2(u64 a, u64 b) {
    u64 r;
    asm("add.rn.f32x2 %0, %1, %2;" : "=l"(r) : "l"(a), "l"(b));
    return r;
}
__device__ __forceinline__ u64 mul2(u64 a, u64 b) {
    u64 r;
    asm("mul.rn.f32x2 %0, %1, %2;" : "=l"(r) : "l"(a), "l"(b));
    return r;
}
__device__ __forceinline__ u64 fma2(u64 a, u64 b, u64 c) {
    u64 r;
    asm("fma.rn.f32x2 %0, %1, %2, %3;" : "=l"(r) : "l"(a), "l"(b), "l"(c));
    return r;
}

// Parallel (predicated-shift) insert into sorted ascending top-K.
// All compares independent -> ~30 cyc depth instead of a 19-step serial
// swap chain (~250 cyc). Strict '<' preserves lax.top_k tie-breaking
// (equal keys keep the earlier-inserted = lower-j element first).
__device__ __forceinline__ void par_insert(float d, int j, float* dist,
                                           int* idx) {
    if (d < dist[KNN - 1]) {
        bool c[KNN];
#pragma unroll
        for (int k = 0; k < KNN; ++k) c[k] = d < dist[k];
#pragma unroll
        for (int k = KNN - 1; k > 0; --k) {
            dist[k] = c[k - 1] ? dist[k - 1] : (c[k] ? d : dist[k]);
            idx[k] = c[k - 1] ? idx[k - 1] : (c[k] ? j : idx[k]);
        }
        if (c[0]) {
            dist[0] = d;
            idx[0] = j;
        }
    }
}

__global__ __launch_bounds__(QPB) void knn_kernel(const float* __restrict__ x,
                                                  float* __restrict__ out) {
    __shared__ float xs[TILE], ys[TILE], zs[TILE];
    __shared__ float2 buf[BUFCAP * QPB];  // per-thread column, interleaved

    const int tid = threadIdx.x;
    const int blocksPerSeg = SEG / QPB;  // 32
    const int seg = blockIdx.x / blocksPerSeg;
    const int base = seg * SEG;
    const int qg = base + (blockIdx.x % blocksPerSeg) * QPB + tid;

    // Key: d_j = xj*(xj+m2x)+yj*(yj+m2y)+zj*(zj+m2z) = |pj|^2 - 2 q.pj
    // (drops the per-query constant |q|^2 -> same ordering).
    const float m2x = -2.0f * x[qg * 3 + 0];
    const float m2y = -2.0f * x[qg * 3 + 1];
    const float m2z = -2.0f * x[qg * 3 + 2];
    const u64 m2x2 = pk2(m2x, m2x);
    const u64 m2y2 = pk2(m2y, m2y);
    const u64 m2z2 = pk2(m2z, m2z);

    float dist[KNN];
    int idx[KNN];
#pragma unroll
    for (int k = 0; k < KNN; ++k) {
        dist[k] = CUDART_INF_F;
        idx[k] = 0;
    }

    float thr = CUDART_INF_F;  // stale copy of dist[KNN-1] (conservative)
    int cnt = 0;               // buffered items this chunk

    // Load tile 0 (points 0..2047 of the segment).
    for (int i = tid; i < TILE; i += QPB) {
        int g = (base + i) * 3;
        xs[i] = x[g + 0];
        ys[i] = x[g + 1];
        zs[i] = x[g + 2];
    }
    __syncthreads();

    const float4* __restrict__ xs4 = (const float4*)xs;
    const float4* __restrict__ ys4 = (const float4*)ys;
    const float4* __restrict__ zs4 = (const float4*)zs;

#define PUSH(dv, jv)                                                         \
    do {                                                                     \
        if ((dv) < thr) {                                                    \
            if (cnt < BUFCAP) {                                              \
                buf[cnt * QPB + tid] =                                       \
                    make_float2((dv), __int_as_float(jv));                   \
                cnt++;                                                       \
            } else {                                                         \
                par_insert((dv), (jv), dist, idx);                           \
            }                                                                \
        }                                                                    \
    } while (0)

    // Doubling-ish drain schedule; all boundaries divisible by 4.
    constexpr int B[NPH + 1] = {0,   20,  32,  48,   72,   108,  164, 248,
                                372, 560, 840, 1260, 1892, 2048, 3072, 4096};

#pragma unroll
    for (int ph = 0; ph < NPH; ++ph) {
        const int s = B[ph], e = B[ph + 1];
        if (s == TILE) {  // switch to tile 1 (points 2048..4095)
            __syncthreads();
            for (int i = tid; i < TILE; i += QPB) {
                int g = (base + TILE + i) * 3;
                xs[i] = x[g + 0];
                ys[i] = x[g + 1];
                zs[i] = x[g + 2];
            }
            __syncthreads();
        }
        const int tb4 = (s >= TILE) ? (TILE / 4) : 0;

#pragma unroll 2
        for (int j4 = s / 4; j4 < e / 4; ++j4) {
            float4 vx = xs4[j4 - tb4];
            float4 vy = ys4[j4 - tb4];
            float4 vz = zs4[j4 - tb4];
            int j = j4 * 4;

            // Packed f32x2 distance eval: 2 candidates per op chain.
            u64 vx01 = pk2(vx.x, vx.y), vx23 = pk2(vx.z, vx.w);
            u64 vy01 = pk2(vy.x, vy.y), vy23 = pk2(vy.z, vy.w);
            u64 vz01 = pk2(vz.x, vz.y), vz23 = pk2(vz.z, vz.w);

            u64 acc01 = mul2(vx01, add2(vx01, m2x2));
            acc01 = fma2(vy01, add2(vy01, m2y2), acc01);
            acc01 = fma2(vz01, add2(vz01, m2z2), acc01);
            u64 acc23 = mul2(vx23, add2(vx23, m2x2));
            acc23 = fma2(vy23, add2(vy23, m2y2), acc23);
            acc23 = fma2(vz23, add2(vz23, m2z2), acc23);

            float d0, d1, d2, d3;
            upk2(d0, d1, acc01);
            upk2(d2, d3, acc23);

            PUSH(d0, j + 0);
            PUSH(d1, j + 1);
            PUSH(d2, j + 2);
            PUSH(d3, j + 3);
        }

        // Drain: insert buffered items in push (= ascending j) order.
        int mx = __reduce_max_sync(0xffffffffu, cnt);
        for (int t = 0; t < mx; ++t) {
            if (t < cnt) {
                float2 en = buf[t * QPB + tid];
                par_insert(en.x, __float_as_int(en.y), dist, idx);
            }
        }
        cnt = 0;
        thr = dist[KNN - 1];  // refresh exact threshold
    }

    // Output global indices as float32 (harness output dtype).
#pragma unroll
    for (int k = 0; k < KNN; ++k) {
        out[qg * KNN + k] = (float)(base + idx[k]);
    }
#undef PUSH
}

extern "C" void kernel_launch(void* const* d_in, const int* in_sizes, int n_in,
                              void* d_out, int out_size) {
    // x is the larger input under both elements and bytes conventions.
    int xi = 0;
    for (int i = 1; i < n_in; ++i)
        if (in_sizes[i] > in_sizes[xi]) xi = i;
    const float* x = (const float*)d_in[xi];
    float* out = (float*)d_out;

    dim3 grid(NPTS / QPB);  // 512 blocks
    knn_kernel<<<grid, QPB>>>(x, out);
}